// round 13
// baseline (speedup 1.0000x reference)
#include <cuda_runtime.h>
#include <cuda_fp16.h>

// NATSearch: 2D neighborhood attention (NATTEN-style). TWO launches:
// qkv GEMM TC (v written fp32) -> FUSED attention (HFMA2 logits, fp32 AV,
// shuffle-paired softmax halves) + proj TC.

#define NIMG   4
#define HW     64
#define CCH    64
#define NHEADS 2
#define DHEAD  32
#define KWIN   7
#define NPIX   (NIMG * HW * HW)   // 16384
#define QKVD   192
#define NBDIM  14
#define NNB    (NBDIM * NBDIM)    // 196
#define FPITCH 72                 // halfs pitch (144B rows)
#define WPITCH 200                // halfs pitch for [c][192] w tile
#define VPITCH 68                 // floats pitch for fp32 v tile (272B rows)
#define QSCALE 0.17677669529663687f

__device__ __align__(16) float  g_q [NPIX * CCH];   // [pix][64] fp32 (pre-scaled)
__device__ __align__(16) __half g_kh[NPIX * CCH];   // [pix][64] fp16
__device__ __align__(16) float  g_v [NPIX * CCH];   // [pix][64] fp32

// ---------------------------------------------------------------------------
__device__ __forceinline__ void ldsm4(unsigned r[4], unsigned addr) {
    asm volatile("ldmatrix.sync.aligned.m8n8.x4.shared.b16 {%0,%1,%2,%3}, [%4];"
                 : "=r"(r[0]), "=r"(r[1]), "=r"(r[2]), "=r"(r[3]) : "r"(addr));
}
__device__ __forceinline__ void ldsm2t(unsigned r[2], unsigned addr) {
    asm volatile("ldmatrix.sync.aligned.m8n8.x2.trans.shared.b16 {%0,%1}, [%2];"
                 : "=r"(r[0]), "=r"(r[1]) : "r"(addr));
}
__device__ __forceinline__ void mma16816(float c[4], const unsigned a[4], const unsigned b[2]) {
    asm volatile(
        "mma.sync.aligned.m16n8k16.row.col.f32.f16.f16.f32 "
        "{%0,%1,%2,%3},{%4,%5,%6,%7},{%8,%9},{%0,%1,%2,%3};"
        : "+f"(c[0]), "+f"(c[1]), "+f"(c[2]), "+f"(c[3])
        : "r"(a[0]), "r"(a[1]), "r"(a[2]), "r"(a[3]), "r"(b[0]), "r"(b[1]));
}

// ---------------------------------------------------------------------------
// Kernel 1: qkv = x @ w_qkv + b_qkv (tensor cores). v written fp32.
// ---------------------------------------------------------------------------
__global__ void __launch_bounds__(256) qkv_tc_kernel(const float* __restrict__ vid,
                                                     const float* __restrict__ w_qkv,
                                                     const float* __restrict__ b_qkv) {
    __shared__ __half xh[64 * FPITCH];    // [px][c]
    __shared__ __half wc[64 * WPITCH];    // [c][j] natural layout

    const int tid  = threadIdx.x;
    const int lane = tid & 31;
    const int warp = tid >> 5;
    const int pix0 = blockIdx.x * 64;
    const int n  = pix0 >> 12;
    const int xr = (pix0 >> 6) & 63;
    const float* vbase = vid + n * 262144 + xr * 64;

#pragma unroll
    for (int it = 0; it < 4; it++) {
        const int i = tid + it * 256;
        const int c = i >> 4, y4 = (i & 15) * 4;
        const float4 t = *(const float4*)(vbase + c * 4096 + y4);
        xh[(y4 + 0) * FPITCH + c] = __float2half(t.x);
        xh[(y4 + 1) * FPITCH + c] = __float2half(t.y);
        xh[(y4 + 2) * FPITCH + c] = __float2half(t.z);
        xh[(y4 + 3) * FPITCH + c] = __float2half(t.w);
    }
#pragma unroll
    for (int it = 0; it < 12; it++) {
        const int i = tid + it * 256;
        const int c = i / 48, jq = i % 48;
        const float4 t = *(const float4*)(w_qkv + c * QKVD + jq * 4);
        __half2 h0 = __floats2half2_rn(t.x, t.y);
        __half2 h1 = __floats2half2_rn(t.z, t.w);
        uint2 u; u.x = *(unsigned*)&h0; u.y = *(unsigned*)&h1;
        *(uint2*)&wc[c * WPITCH + jq * 4] = u;
    }
    __syncthreads();

    const unsigned xbase = (unsigned)__cvta_generic_to_shared(xh);
    const unsigned wbase = (unsigned)__cvta_generic_to_shared(wc);
    const int wn0 = warp * 24;
    const int arow = lane & 15;
    const int acol8 = ((lane >> 4) & 1) * 8;
    const int l16 = lane & 15;

#pragma unroll
    for (int nt = 0; nt < 3; nt++) {
        float acc[4][4];
#pragma unroll
        for (int mt = 0; mt < 4; mt++)
#pragma unroll
            for (int r = 0; r < 4; r++) acc[mt][r] = 0.f;

#pragma unroll
        for (int ks = 0; ks < 4; ks++) {
            unsigned bfr[2];
            ldsm2t(bfr, wbase + (unsigned)((ks * 16 + l16) * WPITCH + wn0 + nt * 8) * 2u);
#pragma unroll
            for (int mt = 0; mt < 4; mt++) {
                unsigned afr[4];
                const int row = mt * 16 + arow;
                const int col = ks * 16 + acol8;
                ldsm4(afr, xbase + (unsigned)(row * FPITCH + col) * 2u);
                mma16816(acc[mt], afr, bfr);
            }
        }

        const int J = wn0 + nt * 8 + 2 * (lane & 3);
        const float b0 = b_qkv[J], b1 = b_qkv[J + 1];
#pragma unroll
        for (int mt = 0; mt < 4; mt++) {
            const int pxa = pix0 + mt * 16 + (lane >> 2);
            const int pxb = pxa + 8;
            if (J < 64) {
                float2 r0 = make_float2((acc[mt][0] + b0) * QSCALE, (acc[mt][1] + b1) * QSCALE);
                float2 r1 = make_float2((acc[mt][2] + b0) * QSCALE, (acc[mt][3] + b1) * QSCALE);
                *(float2*)(g_q + (size_t)pxa * 64 + J) = r0;
                *(float2*)(g_q + (size_t)pxb * 64 + J) = r1;
            } else if (J < 128) {
                const int off = J - 64;
                *(__half2*)(g_kh + (size_t)pxa * 64 + off) = __floats2half2_rn(acc[mt][0] + b0, acc[mt][1] + b1);
                *(__half2*)(g_kh + (size_t)pxb * 64 + off) = __floats2half2_rn(acc[mt][2] + b0, acc[mt][3] + b1);
            } else {
                const int off = J - 128;
                *(float2*)(g_v + (size_t)pxa * 64 + off) = make_float2(acc[mt][0] + b0, acc[mt][1] + b1);
                *(float2*)(g_v + (size_t)pxb * 64 + off) = make_float2(acc[mt][2] + b0, acc[mt][3] + b1);
            }
        }
    }
}

// ---------------------------------------------------------------------------
// Kernel 2: FUSED attention + proj. 256 thr. Query-halves are ADJACENT lanes
// (half = tid&1) -> softmax combine via shfl, no scratch, 2 syncs total.
// ---------------------------------------------------------------------------
#define OFF_KS   0
#define OFF_VSF  (NNB * FPITCH * 2)                    // 28224
#define OFF_RS   (OFF_VSF + NNB * VPITCH * 4)          // 81536
#define OFF_ATTS (OFF_RS + 344 * 4)                    // 82912
#define OFF_WPS  (OFF_ATTS + 64 * FPITCH * 2)          // 92128
#define SMEM_FUSED (OFF_WPS + 64 * FPITCH * 2)         // 101344 (~99 KB)

__global__ void __launch_bounds__(256) attnproj_kernel(const float* __restrict__ rpb,
                                                       const float* __restrict__ w_proj,
                                                       const float* __restrict__ b_proj,
                                                       float* __restrict__ out, int out_size) {
    extern __shared__ char smraw[];
    __half* ks   = (__half*)(smraw + OFF_KS);      // [196][FPITCH] fp16
    float*  vsf  = (float*) (smraw + OFF_VSF);     // [196][VPITCH] fp32
    float*  rs   = (float*) (smraw + OFF_RS);      // [2][169]
    __half* atts = (__half*)(smraw + OFF_ATTS);    // [64][FPITCH]
    __half* wps  = (__half*)(smraw + OFF_WPS);     // [c][j] natural

    const int tid  = threadIdx.x;
    const int lane = tid & 31;
    const int warp = tid >> 5;
    const int half = tid & 1;                      // position-half, adjacent lanes
    const int qid  = (tid >> 1) & 63;
    const int head = tid >> 7;
    const int n    = blockIdx.y;
    const int x0   = (blockIdx.x >> 3) * 8;
    const int y0   = (blockIdx.x & 7) * 8;
    const int rb   = min(max(x0 - 3, 0), 50);
    const int cb   = min(max(y0 - 3, 0), 50);

    const int qx = qid >> 3, qy = qid & 7;
    const int xx = x0 + qx, yy = y0 + qy;
    const int hb = head * DHEAD;
    const int pix = n * 4096 + xx * 64 + yy;

    // q -> 16 half2 regs (global load overlaps staging)
    __half2 qh[16];
    {
        const float* qp = g_q + (size_t)pix * 64 + hb;
#pragma unroll
        for (int dq = 0; dq < 8; dq++) {
            const float4 t = *(const float4*)(qp + dq * 4);
            qh[dq * 2 + 0] = __floats2half2_rn(t.x, t.y);
            qh[dq * 2 + 1] = __floats2half2_rn(t.z, t.w);
        }
    }

    // stage k (fp16, 8 uint4/row) and v (fp32, 16 float4/row)
    for (int i = tid; i < NNB * 8; i += 256) {
        const int nb = i >> 3, part = i & 7;
        const int gr = rb + nb / NBDIM, gc = cb + nb % NBDIM;
        *(uint4*)(ks + nb * FPITCH + part * 8) =
            *(const uint4*)(g_kh + (size_t)(n * 4096 + gr * 64 + gc) * 64 + part * 8);
    }
    for (int i = tid; i < NNB * 16; i += 256) {
        const int nb = i >> 4, part = i & 15;
        const int gr = rb + nb / NBDIM, gc = cb + nb % NBDIM;
        *(float4*)(vsf + nb * VPITCH + part * 4) =
            *(const float4*)(g_v + (size_t)(n * 4096 + gr * 64 + gc) * 64 + part * 4);
    }
    for (int i = tid; i < 2 * 169; i += 256) rs[i] = rpb[i];
#pragma unroll
    for (int it = 0; it < 4; it++) {               // w_proj: coalesced convert [c][j]
        const int i = tid + it * 256;
        const int c = i >> 4, jq = i & 15;
        const float4 t = *(const float4*)(w_proj + c * 64 + jq * 4);
        __half2 h0 = __floats2half2_rn(t.x, t.y);
        __half2 h1 = __floats2half2_rn(t.z, t.w);
        uint2 u; u.x = *(unsigned*)&h0; u.y = *(unsigned*)&h1;
        *(uint2*)&wps[c * FPITCH + jq * 4] = u;
    }
    __syncthreads();

    const int sx = min(max(xx - 3, 0), 57), sy = min(max(yy - 3, 0), 57);
    const int r0 = sx - rb, c0 = sy - cb;
    const int bh = sx - xx + 6, bw = sy - yy + 6;
    const float* rh = rs + head * 169;

    const int pbase = half * 25;
    const int pcnt  = 25 - half;                   // 25 / 24

    float lg[25];
    float m = -1e30f;
#pragma unroll
    for (int pp = 0; pp < 25; pp++) {
        if (pp < pcnt) {
            const int p = pbase + pp;
            const int a = p / 7, b = p % 7;
            const __half* kp = ks + ((r0 + a) * NBDIM + c0 + b) * FPITCH + hb;
            __half2 a0 = __float2half2_rn(0.f), a1 = a0, a2 = a0, a3 = a0;
#pragma unroll
            for (int u = 0; u < 4; u++) {
                const uint4 r = *(const uint4*)(kp + u * 8);
                a0 = __hfma2(qh[u * 4 + 0], *(const __half2*)&r.x, a0);
                a1 = __hfma2(qh[u * 4 + 1], *(const __half2*)&r.y, a1);
                a2 = __hfma2(qh[u * 4 + 2], *(const __half2*)&r.z, a2);
                a3 = __hfma2(qh[u * 4 + 3], *(const __half2*)&r.w, a3);
            }
            const __half2 hs = __hadd2(__hadd2(a0, a1), __hadd2(a2, a3));
            const float2 fs = __half22float2(hs);
            lg[pp] = fs.x + fs.y + rh[(bh + a) * 13 + bw + b];
            m = fmaxf(m, lg[pp]);
        }
    }

    // softmax across the lane pair
    m = fmaxf(m, __shfl_xor_sync(0xFFFFFFFFu, m, 1));
    float s = 0.f;
#pragma unroll
    for (int pp = 0; pp < 25; pp++) {
        if (pp < pcnt) { const float e = __expf(lg[pp] - m); lg[pp] = e; s += e; }
    }
    const float stot = s + __shfl_xor_sync(0xFFFFFFFFu, s, 1);
    const float inv = 1.0f / stot;

    float o[32];
#pragma unroll
    for (int d = 0; d < 32; d++) o[d] = 0.f;
#pragma unroll
    for (int pp = 0; pp < 25; pp++) {
        if (pp < pcnt) {
            const int p = pbase + pp;
            const int a = p / 7, b = p % 7;
            const float w = lg[pp];
            const float* vp = vsf + ((r0 + a) * NBDIM + c0 + b) * VPITCH + hb;
#pragma unroll
            for (int u = 0; u < 8; u++) {
                const float4 v4 = *(const float4*)(vp + u * 4);
                o[u * 4 + 0] += w * v4.x; o[u * 4 + 1] += w * v4.y;
                o[u * 4 + 2] += w * v4.z; o[u * 4 + 3] += w * v4.w;
            }
        }
    }

    // combine halves via shuffle; even lane writes the att tile
#pragma unroll
    for (int d = 0; d < 32; d++) o[d] += __shfl_xor_sync(0xFFFFFFFFu, o[d], 1);
    if (half == 0) {
        __align__(16) __half2 hh[16];
#pragma unroll
        for (int d2 = 0; d2 < 16; d2++)
            hh[d2] = __floats2half2_rn(o[d2 * 2 + 0] * inv, o[d2 * 2 + 1] * inv);
        uint4* dst = (uint4*)(atts + qid * FPITCH + hb);
        const uint4* src = (const uint4*)hh;
        dst[0] = src[0]; dst[1] = src[1]; dst[2] = src[2]; dst[3] = src[3];
    }
    __syncthreads();

    // ---- fused proj: out[64px x 64j] = atts @ w_proj + b_proj ----
    const unsigned abase = (unsigned)__cvta_generic_to_shared(atts);
    const unsigned wbase = (unsigned)__cvta_generic_to_shared(wps);
    const int j0 = warp * 8;
    const int arow = lane & 15;
    const int acol8 = ((lane >> 4) & 1) * 8;
    const int l16 = lane & 15;

    float acc[4][4];
#pragma unroll
    for (int mt = 0; mt < 4; mt++)
#pragma unroll
        for (int r = 0; r < 4; r++) acc[mt][r] = 0.f;

#pragma unroll
    for (int kk = 0; kk < 4; kk++) {
        unsigned bfr[2];
        ldsm2t(bfr, wbase + (unsigned)((kk * 16 + l16) * FPITCH + j0) * 2u);
#pragma unroll
        for (int mt = 0; mt < 4; mt++) {
            unsigned afr[4];
            const int row = mt * 16 + arow;
            ldsm4(afr, abase + (unsigned)(row * FPITCH + kk * 16 + acol8) * 2u);
            mma16816(acc[mt], afr, bfr);
        }
    }

    const int J = j0 + 2 * (lane & 3);
    const float b0 = b_proj[J], b1 = b_proj[J + 1];
#pragma unroll
    for (int mt = 0; mt < 4; mt++) {
#pragma unroll
        for (int rr = 0; rr < 2; rr++) {
            const int row = mt * 16 + (lane >> 2) + rr * 8;
            const int opix = n * 4096 + (x0 + (row >> 3)) * 64 + (y0 + (row & 7));
            *(float2*)(out + (size_t)opix * 64 + J) =
                make_float2(acc[mt][rr * 2 + 0] + b0, acc[mt][rr * 2 + 1] + b1);
        }
    }

    if (blockIdx.x == 0 && blockIdx.y == 0) {
        for (int i = NPIX * CCH + tid; i < out_size; i += 256) out[i] = 0.0f;
    }
}

// ---------------------------------------------------------------------------
extern "C" void kernel_launch(void* const* d_in, const int* in_sizes, int n_in,
                              void* d_out, int out_size) {
    const float* vid    = (const float*)d_in[0];
    const float* w_qkv  = (const float*)d_in[4];
    const float* b_qkv  = (const float*)d_in[5];
    const float* rpb    = (const float*)d_in[6];
    const float* w_proj = (const float*)d_in[7];
    const float* b_proj = (const float*)d_in[8];
    float* out = (float*)d_out;

    qkv_tc_kernel<<<NPIX / 64, 256>>>(vid, w_qkv, b_qkv);

    cudaFuncSetAttribute(attnproj_kernel, cudaFuncAttributeMaxDynamicSharedMemorySize, SMEM_FUSED);
    attnproj_kernel<<<dim3(64, NIMG), 256, SMEM_FUSED>>>(rpb, w_proj, b_proj, out, out_size);
}

// round 14
// speedup vs baseline: 1.3538x; 1.3538x over previous
#include <cuda_runtime.h>
#include <cuda_fp16.h>

// NATSearch: 2D neighborhood attention (NATTEN-style). TWO launches:
// qkv GEMM TC -> FUSED attention (HFMA2 logits, fp16 k/v, fp32 softmax/AV)
// + proj TC. R11 structure with only the logit inner loop changed.

#define NIMG   4
#define HW     64
#define CCH    64
#define NHEADS 2
#define DHEAD  32
#define KWIN   7
#define NPIX   (NIMG * HW * HW)   // 16384
#define QKVD   192
#define NBDIM  14
#define NNB    (NBDIM * NBDIM)    // 196
#define FPITCH 72                 // halfs pitch (144B rows)
#define WPITCH 200                // halfs pitch for [c][192] w tile
#define QSCALE 0.17677669529663687f

__device__ __align__(16) float  g_q [NPIX * CCH];   // [pix][64] fp32 (pre-scaled)
__device__ __align__(16) __half g_kh[NPIX * CCH];   // [pix][64] fp16
__device__ __align__(16) __half g_vh[NPIX * CCH];   // [pix][64] fp16

// ---------------------------------------------------------------------------
__device__ __forceinline__ void ldsm4(unsigned r[4], unsigned addr) {
    asm volatile("ldmatrix.sync.aligned.m8n8.x4.shared.b16 {%0,%1,%2,%3}, [%4];"
                 : "=r"(r[0]), "=r"(r[1]), "=r"(r[2]), "=r"(r[3]) : "r"(addr));
}
__device__ __forceinline__ void ldsm2t(unsigned r[2], unsigned addr) {
    asm volatile("ldmatrix.sync.aligned.m8n8.x2.trans.shared.b16 {%0,%1}, [%2];"
                 : "=r"(r[0]), "=r"(r[1]) : "r"(addr));
}
__device__ __forceinline__ void mma16816(float c[4], const unsigned a[4], const unsigned b[2]) {
    asm volatile(
        "mma.sync.aligned.m16n8k16.row.col.f32.f16.f16.f32 "
        "{%0,%1,%2,%3},{%4,%5,%6,%7},{%8,%9},{%0,%1,%2,%3};"
        : "+f"(c[0]), "+f"(c[1]), "+f"(c[2]), "+f"(c[3])
        : "r"(a[0]), "r"(a[1]), "r"(a[2]), "r"(a[3]), "r"(b[0]), "r"(b[1]));
}

// ---------------------------------------------------------------------------
// Kernel 1: qkv = x @ w_qkv + b_qkv (tensor cores). Unchanged from R11.
// ---------------------------------------------------------------------------
__global__ void __launch_bounds__(256) qkv_tc_kernel(const float* __restrict__ vid,
                                                     const float* __restrict__ w_qkv,
                                                     const float* __restrict__ b_qkv) {
    __shared__ __half xh[64 * FPITCH];    // [px][c]
    __shared__ __half wc[64 * WPITCH];    // [c][j] natural layout

    const int tid  = threadIdx.x;
    const int lane = tid & 31;
    const int warp = tid >> 5;
    const int pix0 = blockIdx.x * 64;
    const int n  = pix0 >> 12;
    const int xr = (pix0 >> 6) & 63;
    const float* vbase = vid + n * 262144 + xr * 64;

#pragma unroll
    for (int it = 0; it < 4; it++) {
        const int i = tid + it * 256;
        const int c = i >> 4, y4 = (i & 15) * 4;
        const float4 t = *(const float4*)(vbase + c * 4096 + y4);
        xh[(y4 + 0) * FPITCH + c] = __float2half(t.x);
        xh[(y4 + 1) * FPITCH + c] = __float2half(t.y);
        xh[(y4 + 2) * FPITCH + c] = __float2half(t.z);
        xh[(y4 + 3) * FPITCH + c] = __float2half(t.w);
    }
#pragma unroll
    for (int it = 0; it < 12; it++) {
        const int i = tid + it * 256;
        const int c = i / 48, jq = i % 48;
        const float4 t = *(const float4*)(w_qkv + c * QKVD + jq * 4);
        __half2 h0 = __floats2half2_rn(t.x, t.y);
        __half2 h1 = __floats2half2_rn(t.z, t.w);
        uint2 u; u.x = *(unsigned*)&h0; u.y = *(unsigned*)&h1;
        *(uint2*)&wc[c * WPITCH + jq * 4] = u;
    }
    __syncthreads();

    const unsigned xbase = (unsigned)__cvta_generic_to_shared(xh);
    const unsigned wbase = (unsigned)__cvta_generic_to_shared(wc);
    const int wn0 = warp * 24;
    const int arow = lane & 15;
    const int acol8 = ((lane >> 4) & 1) * 8;
    const int l16 = lane & 15;

#pragma unroll
    for (int nt = 0; nt < 3; nt++) {
        float acc[4][4];
#pragma unroll
        for (int mt = 0; mt < 4; mt++)
#pragma unroll
            for (int r = 0; r < 4; r++) acc[mt][r] = 0.f;

#pragma unroll
        for (int ks = 0; ks < 4; ks++) {
            unsigned bfr[2];
            ldsm2t(bfr, wbase + (unsigned)((ks * 16 + l16) * WPITCH + wn0 + nt * 8) * 2u);
#pragma unroll
            for (int mt = 0; mt < 4; mt++) {
                unsigned afr[4];
                const int row = mt * 16 + arow;
                const int col = ks * 16 + acol8;
                ldsm4(afr, xbase + (unsigned)(row * FPITCH + col) * 2u);
                mma16816(acc[mt], afr, bfr);
            }
        }

        const int J = wn0 + nt * 8 + 2 * (lane & 3);
        const float b0 = b_qkv[J], b1 = b_qkv[J + 1];
#pragma unroll
        for (int mt = 0; mt < 4; mt++) {
            const int pxa = pix0 + mt * 16 + (lane >> 2);
            const int pxb = pxa + 8;
            if (J < 64) {
                float2 r0 = make_float2((acc[mt][0] + b0) * QSCALE, (acc[mt][1] + b1) * QSCALE);
                float2 r1 = make_float2((acc[mt][2] + b0) * QSCALE, (acc[mt][3] + b1) * QSCALE);
                *(float2*)(g_q + (size_t)pxa * 64 + J) = r0;
                *(float2*)(g_q + (size_t)pxb * 64 + J) = r1;
            } else if (J < 128) {
                const int off = J - 64;
                *(__half2*)(g_kh + (size_t)pxa * 64 + off) = __floats2half2_rn(acc[mt][0] + b0, acc[mt][1] + b1);
                *(__half2*)(g_kh + (size_t)pxb * 64 + off) = __floats2half2_rn(acc[mt][2] + b0, acc[mt][3] + b1);
            } else {
                const int off = J - 128;
                *(__half2*)(g_vh + (size_t)pxa * 64 + off) = __floats2half2_rn(acc[mt][0] + b0, acc[mt][1] + b1);
                *(__half2*)(g_vh + (size_t)pxb * 64 + off) = __floats2half2_rn(acc[mt][2] + b0, acc[mt][3] + b1);
            }
        }
    }
}

// ---------------------------------------------------------------------------
// Kernel 2: FUSED attention + proj (R11 structure). 256 thr = 64 q x 2 heads
// x 2 position-halves. HFMA2 logit inner loop; everything else as R11.
// ---------------------------------------------------------------------------
#define OFF_KS   0
#define OFF_VS   (NNB * FPITCH * 2)                    // 28224
#define OFF_RS   (OFF_VS + NNB * FPITCH * 2)           // 56448
#define OFF_PM   (OFF_RS + 344 * 4)
#define OFF_PS   (OFF_PM + 256 * 4)
#define OFF_ATTS (OFF_PS + 256 * 4)
#define OFF_WPS  (OFF_ATTS + 64 * FPITCH * 2)
#define SMEM_FUSED (OFF_WPS + 64 * FPITCH * 2)

__global__ void __launch_bounds__(256) attnproj_kernel(const float* __restrict__ rpb,
                                                       const float* __restrict__ w_proj,
                                                       const float* __restrict__ b_proj,
                                                       float* __restrict__ out, int out_size) {
    extern __shared__ char smraw[];
    __half* ks   = (__half*)(smraw + OFF_KS);      // [196][FPITCH]
    __half* vs   = (__half*)(smraw + OFF_VS);      // [196][FPITCH]
    float*  rs   = (float*) (smraw + OFF_RS);      // [2][169]
    float*  pm   = (float*) (smraw + OFF_PM);      // [256]
    float*  ps   = (float*) (smraw + OFF_PS);      // [256]
    __half* atts = (__half*)(smraw + OFF_ATTS);    // [64][FPITCH]
    __half* wps  = (__half*)(smraw + OFF_WPS);     // [c][j] natural
    float*  os   = (float*) (smraw + OFF_KS);      // [2][64][33] aliases ks

    const int tid  = threadIdx.x;
    const int lane = tid & 31;
    const int warp = tid >> 5;
    const int qid  = tid & 63;
    const int head = (tid >> 6) & 1;
    const int half = tid >> 7;
    const int n    = blockIdx.y;
    const int x0   = (blockIdx.x >> 3) * 8;
    const int y0   = (blockIdx.x & 7) * 8;
    const int rb   = min(max(x0 - 3, 0), 50);
    const int cb   = min(max(y0 - 3, 0), 50);

    const int qx = qid >> 3, qy = qid & 7;
    const int xx = x0 + qx, yy = y0 + qy;
    const int hb = head * DHEAD;
    const int pix = n * 4096 + xx * 64 + yy;

    // q -> 16 half2 regs (global load overlaps staging)
    __half2 qh[16];
    {
        const float* qp = g_q + (size_t)pix * 64 + hb;
#pragma unroll
        for (int dq = 0; dq < 8; dq++) {
            const float4 t = *(const float4*)(qp + dq * 4);
            qh[dq * 2 + 0] = __floats2half2_rn(t.x, t.y);
            qh[dq * 2 + 1] = __floats2half2_rn(t.z, t.w);
        }
    }

    // stage k/v (BOTH heads, full 64 ch): 196 x 16 uint4
    for (int i = tid; i < NNB * 16; i += 256) {
        const int nb = i >> 4, part = i & 15;
        const int gr = rb + nb / NBDIM, gc = cb + nb % NBDIM;
        const size_t psrc = (size_t)(n * 4096 + gr * 64 + gc) * 64;
        if (part < 8)
            *(uint4*)(ks + nb * FPITCH + part * 8) = *(const uint4*)(g_kh + psrc + part * 8);
        else
            *(uint4*)(vs + nb * FPITCH + (part - 8) * 8) = *(const uint4*)(g_vh + psrc + (part - 8) * 8);
    }
    for (int i = tid; i < 2 * 169; i += 256) rs[i] = rpb[i];
#pragma unroll
    for (int it = 0; it < 4; it++) {               // w_proj: coalesced convert [c][j]
        const int i = tid + it * 256;
        const int c = i >> 4, jq = i & 15;
        const float4 t = *(const float4*)(w_proj + c * 64 + jq * 4);
        __half2 h0 = __floats2half2_rn(t.x, t.y);
        __half2 h1 = __floats2half2_rn(t.z, t.w);
        uint2 u; u.x = *(unsigned*)&h0; u.y = *(unsigned*)&h1;
        *(uint2*)&wps[c * FPITCH + jq * 4] = u;
    }
    __syncthreads();

    const int sx = min(max(xx - 3, 0), 57), sy = min(max(yy - 3, 0), 57);
    const int r0 = sx - rb, c0 = sy - cb;
    const int bh = sx - xx + 6, bw = sy - yy + 6;
    const float* rh = rs + head * 169;

    const int pbase = half * 25;
    const int pcnt  = 25 - half;        // 25 / 24

    float lg[25];
    float m = -1e30f;
#pragma unroll
    for (int pp = 0; pp < 25; pp++) {
        if (pp < pcnt) {
            const int p = pbase + pp;
            const int a = p / 7, b = p % 7;
            const __half* kp = ks + ((r0 + a) * NBDIM + c0 + b) * FPITCH + hb;
            __half2 a0 = __float2half2_rn(0.f), a1 = a0, a2 = a0, a3 = a0;
#pragma unroll
            for (int u = 0; u < 4; u++) {
                const uint4 r = *(const uint4*)(kp + u * 8);
                a0 = __hfma2(qh[u * 4 + 0], *(const __half2*)&r.x, a0);
                a1 = __hfma2(qh[u * 4 + 1], *(const __half2*)&r.y, a1);
                a2 = __hfma2(qh[u * 4 + 2], *(const __half2*)&r.z, a2);
                a3 = __hfma2(qh[u * 4 + 3], *(const __half2*)&r.w, a3);
            }
            const __half2 hs = __hadd2(__hadd2(a0, a1), __hadd2(a2, a3));
            const float2 fs = __half22float2(hs);
            lg[pp] = fs.x + fs.y + rh[(bh + a) * 13 + bw + b];
            m = fmaxf(m, lg[pp]);
        }
    }

    pm[tid] = m;
    __syncthreads();
    m = fmaxf(pm[tid & 127], pm[(tid & 127) + 128]);

    float s = 0.f;
#pragma unroll
    for (int pp = 0; pp < 25; pp++) {
        if (pp < pcnt) { const float e = __expf(lg[pp] - m); lg[pp] = e; s += e; }
    }
    ps[tid] = s;
    __syncthreads();                                // all ks reads complete after this
    const float inv = 1.0f / (ps[tid & 127] + ps[(tid & 127) + 128]);

    float o[32];
#pragma unroll
    for (int d = 0; d < 32; d++) o[d] = 0.f;
#pragma unroll
    for (int pp = 0; pp < 25; pp++) {
        if (pp < pcnt) {
            const int p = pbase + pp;
            const int a = p / 7, b = p % 7;
            const float w = lg[pp];
            const __half* vp = vs + ((r0 + a) * NBDIM + c0 + b) * FPITCH + hb;
#pragma unroll
            for (int u = 0; u < 4; u++) {
                const uint4 r = *(const uint4*)(vp + u * 8);
                const float2 f0 = __half22float2(*(const __half2*)&r.x);
                const float2 f1 = __half22float2(*(const __half2*)&r.y);
                const float2 f2 = __half22float2(*(const __half2*)&r.z);
                const float2 f3 = __half22float2(*(const __half2*)&r.w);
                o[u * 8 + 0] += w * f0.x; o[u * 8 + 1] += w * f0.y;
                o[u * 8 + 2] += w * f1.x; o[u * 8 + 3] += w * f1.y;
                o[u * 8 + 4] += w * f2.x; o[u * 8 + 5] += w * f2.y;
                o[u * 8 + 6] += w * f3.x; o[u * 8 + 7] += w * f3.y;
            }
        }
    }

    // combine halves -> att tile [qid][64ch] fp16 in smem
    if (half == 1) {
        float* od = os + (size_t)(head * 64 + qid) * 33;
#pragma unroll
        for (int d = 0; d < 32; d++) od[d] = o[d];
    }
    __syncthreads();
    if (half == 0) {
        const float* o1 = os + (size_t)(head * 64 + qid) * 33;
        __align__(16) __half2 hh[16];
#pragma unroll
        for (int d2 = 0; d2 < 16; d2++) {
            hh[d2] = __floats2half2_rn((o[d2 * 2 + 0] + o1[d2 * 2 + 0]) * inv,
                                       (o[d2 * 2 + 1] + o1[d2 * 2 + 1]) * inv);
        }
        uint4* dst = (uint4*)(atts + qid * FPITCH + hb);
        const uint4* src = (const uint4*)hh;
        dst[0] = src[0]; dst[1] = src[1]; dst[2] = src[2]; dst[3] = src[3];
    }
    __syncthreads();

    // ---- fused proj: out[64px x 64j] = atts @ w_proj + b_proj ----
    const unsigned abase = (unsigned)__cvta_generic_to_shared(atts);
    const unsigned wbase = (unsigned)__cvta_generic_to_shared(wps);
    const int j0 = warp * 8;
    const int arow = lane & 15;
    const int acol8 = ((lane >> 4) & 1) * 8;
    const int l16 = lane & 15;

    float acc[4][4];
#pragma unroll
    for (int mt = 0; mt < 4; mt++)
#pragma unroll
        for (int r = 0; r < 4; r++) acc[mt][r] = 0.f;

#pragma unroll
    for (int kk = 0; kk < 4; kk++) {
        unsigned bfr[2];
        ldsm2t(bfr, wbase + (unsigned)((kk * 16 + l16) * FPITCH + j0) * 2u);
#pragma unroll
        for (int mt = 0; mt < 4; mt++) {
            unsigned afr[4];
            const int row = mt * 16 + arow;
            ldsm4(afr, abase + (unsigned)(row * FPITCH + kk * 16 + acol8) * 2u);
            mma16816(acc[mt], afr, bfr);
        }
    }

    const int J = j0 + 2 * (lane & 3);
    const float b0 = b_proj[J], b1 = b_proj[J + 1];
#pragma unroll
    for (int mt = 0; mt < 4; mt++) {
#pragma unroll
        for (int rr = 0; rr < 2; rr++) {
            const int row = mt * 16 + (lane >> 2) + rr * 8;
            const int opix = n * 4096 + (x0 + (row >> 3)) * 64 + (y0 + (row & 7));
            *(float2*)(out + (size_t)opix * 64 + J) =
                make_float2(acc[mt][rr * 2 + 0] + b0, acc[mt][rr * 2 + 1] + b1);
        }
    }

    if (blockIdx.x == 0 && blockIdx.y == 0) {
        for (int i = NPIX * CCH + tid; i < out_size; i += 256) out[i] = 0.0f;
    }
}

// ---------------------------------------------------------------------------
extern "C" void kernel_launch(void* const* d_in, const int* in_sizes, int n_in,
                              void* d_out, int out_size) {
    const float* vid    = (const float*)d_in[0];
    const float* w_qkv  = (const float*)d_in[4];
    const float* b_qkv  = (const float*)d_in[5];
    const float* rpb    = (const float*)d_in[6];
    const float* w_proj = (const float*)d_in[7];
    const float* b_proj = (const float*)d_in[8];
    float* out = (float*)d_out;

    qkv_tc_kernel<<<NPIX / 64, 256>>>(vid, w_qkv, b_qkv);

    cudaFuncSetAttribute(attnproj_kernel, cudaFuncAttributeMaxDynamicSharedMemorySize, SMEM_FUSED);
    attnproj_kernel<<<dim3(64, NIMG), 256, SMEM_FUSED>>>(rpb, w_proj, b_proj, out, out_size);
}